// round 2
// baseline (speedup 1.0000x reference)
#include <cuda_runtime.h>
#include <cstdint>

#define SEQ 4096
#define NB 8
#define DM 1024
#define MTOT 32768   // NB*SEQ

// Scratch (device globals: the sanctioned no-alloc workaround)
__device__ float g_Q[(size_t)MTOT * DM];
__device__ float g_K[(size_t)MTOT * DM];
__device__ float g_V[(size_t)MTOT * DM];
__device__ float g_MID[(size_t)MTOT * DM];

__device__ __forceinline__ uint32_t f2tf(float x) {
    uint32_t r;
    asm("cvt.rna.tf32.f32 %0, %1;" : "=r"(r) : "f"(x));
    return r;
}

__device__ __forceinline__ void mma_tf32(float* c, const uint32_t* a, const uint32_t* b) {
    asm volatile(
        "mma.sync.aligned.m16n8k8.row.col.f32.tf32.tf32.f32 "
        "{%0,%1,%2,%3}, {%4,%5,%6,%7}, {%8,%9}, {%0,%1,%2,%3};\n"
        : "+f"(c[0]), "+f"(c[1]), "+f"(c[2]), "+f"(c[3])
        : "r"(a[0]), "r"(a[1]), "r"(a[2]), "r"(a[3]), "r"(b[0]), "r"(b[1]));
}

// ---------------------------------------------------------------------------
// GEMM: C[m,n] = sum_k A[m,k] * B[n,k]   (A row-major MxK, B row-major NxK)
// MODE 0: A = x, three B matrices (Wq,Wk,Wv), C -> g_Q/g_K/g_V (grid.x = 24)
// MODE 1: A = g_MID, B = Wo, C = d_out + bias                  (grid.x = 8)
// Tiles: 128x128x32, 256 threads, warp grid 4(m) x 2(n), warp tile 32x64.
// ---------------------------------------------------------------------------
template <int MODE>
__global__ void __launch_bounds__(256) gemm_k(
    const float* __restrict__ Ain, const float* __restrict__ W0,
    const float* __restrict__ W1, const float* __restrict__ W2,
    const float* __restrict__ bias, float* __restrict__ Cout)
{
    __shared__ uint32_t As[128 * 36];
    __shared__ uint32_t Bs[128 * 36];

    const int tid = threadIdx.x;
    const int lane = tid & 31;
    const int wid = tid >> 5;
    const int wm = wid & 3;
    const int wn = wid >> 2;

    const float* A;
    const float* Bmat;
    float* C;
    int ncol0;
    if (MODE == 0) {
        A = Ain;
        int w = blockIdx.x >> 3;
        Bmat = (w == 0) ? W0 : (w == 1) ? W1 : W2;
        C = (w == 0) ? g_Q : (w == 1) ? g_K : g_V;
        ncol0 = (blockIdx.x & 7) * 128;
    } else {
        A = g_MID;
        Bmat = W0;
        C = Cout;
        ncol0 = blockIdx.x * 128;
    }
    const int mrow0 = blockIdx.y * 128;

    int rr[4], cc[4];
#pragma unroll
    for (int f = 0; f < 4; f++) {
        int idx = f * 256 + tid;
        rr[f] = idx >> 3;
        cc[f] = (idx & 7) * 4;
    }
    const float* Ag = A + (size_t)mrow0 * DM;
    const float* Bg = Bmat + (size_t)ncol0 * DM;

    float acc[2][8][4];
#pragma unroll
    for (int mt = 0; mt < 2; mt++)
#pragma unroll
        for (int nt = 0; nt < 8; nt++)
#pragma unroll
            for (int i = 0; i < 4; i++) acc[mt][nt][i] = 0.f;

    float4 abuf[4], bbuf[4];
#pragma unroll
    for (int f = 0; f < 4; f++) {
        abuf[f] = *(const float4*)(Ag + (size_t)rr[f] * DM + cc[f]);
        bbuf[f] = *(const float4*)(Bg + (size_t)rr[f] * DM + cc[f]);
    }
#pragma unroll
    for (int f = 0; f < 4; f++) {
        uint4 ua = make_uint4(f2tf(abuf[f].x), f2tf(abuf[f].y), f2tf(abuf[f].z), f2tf(abuf[f].w));
        *(uint4*)&As[rr[f] * 36 + cc[f]] = ua;
        uint4 ub = make_uint4(f2tf(bbuf[f].x), f2tf(bbuf[f].y), f2tf(bbuf[f].z), f2tf(bbuf[f].w));
        *(uint4*)&Bs[rr[f] * 36 + cc[f]] = ub;
    }
    __syncthreads();

    for (int kt = 0; kt < 32; kt++) {
        if (kt < 31) {
            const float* Agn = Ag + (kt + 1) * 32;
            const float* Bgn = Bg + (kt + 1) * 32;
#pragma unroll
            for (int f = 0; f < 4; f++) {
                abuf[f] = *(const float4*)(Agn + (size_t)rr[f] * DM + cc[f]);
                bbuf[f] = *(const float4*)(Bgn + (size_t)rr[f] * DM + cc[f]);
            }
        }
#pragma unroll
        for (int kk = 0; kk < 32; kk += 8) {
            uint32_t a[2][4], b[8][2];
#pragma unroll
            for (int mt = 0; mt < 2; mt++) {
                int r0 = wm * 32 + mt * 16 + (lane >> 2);
                const uint32_t* p = &As[r0 * 36 + kk + (lane & 3)];
                a[mt][0] = p[0];
                a[mt][1] = p[8 * 36];
                a[mt][2] = p[4];
                a[mt][3] = p[8 * 36 + 4];
            }
#pragma unroll
            for (int nt = 0; nt < 8; nt++) {
                int c0 = wn * 64 + nt * 8 + (lane >> 2);
                const uint32_t* p = &Bs[c0 * 36 + kk + (lane & 3)];
                b[nt][0] = p[0];
                b[nt][1] = p[4];
            }
#pragma unroll
            for (int mt = 0; mt < 2; mt++)
#pragma unroll
                for (int nt = 0; nt < 8; nt++)
                    mma_tf32(acc[mt][nt], a[mt], b[nt]);
        }
        __syncthreads();
        if (kt < 31) {
#pragma unroll
            for (int f = 0; f < 4; f++) {
                uint4 ua = make_uint4(f2tf(abuf[f].x), f2tf(abuf[f].y), f2tf(abuf[f].z), f2tf(abuf[f].w));
                *(uint4*)&As[rr[f] * 36 + cc[f]] = ua;
                uint4 ub = make_uint4(f2tf(bbuf[f].x), f2tf(bbuf[f].y), f2tf(bbuf[f].z), f2tf(bbuf[f].w));
                *(uint4*)&Bs[rr[f] * 36 + cc[f]] = ub;
            }
            __syncthreads();
        }
    }

#pragma unroll
    for (int mt = 0; mt < 2; mt++) {
#pragma unroll
        for (int nt = 0; nt < 8; nt++) {
            int r = mrow0 + wm * 32 + mt * 16 + (lane >> 2);
            int c = ncol0 + wn * 64 + nt * 8 + 2 * (lane & 3);
            float b0 = 0.f, b1 = 0.f;
            if (MODE == 1) { b0 = bias[c]; b1 = bias[c + 1]; }
            float2 v0 = make_float2(acc[mt][nt][0] + b0, acc[mt][nt][1] + b1);
            *(float2*)&C[(size_t)r * DM + c] = v0;
            float2 v1 = make_float2(acc[mt][nt][2] + b0, acc[mt][nt][3] + b1);
            *(float2*)&C[(size_t)(r + 8) * DM + c] = v1;
        }
    }
}

// ---------------------------------------------------------------------------
// Attention-over-heads. One warp per token position p = n*4096 + s.
// att[i,j] = sum_d Q[p, 64i+d] * K[p, 64j+d]   (16x16x64)
// P = softmax(att / 8) over j
// o[i,d]  = sum_j P[i,j] * V[p, 64j+d]
// Scatter (reshape): MID[n, i*256 + (s>>4), (s&15)*64 + d] = o[i,d]
// ---------------------------------------------------------------------------
__global__ void __launch_bounds__(64) attn_k() {
    __shared__ float sm[2][3536];   // per warp: q[16*68] k[16*68] v[16*68] att[16*17]
    const int lane = threadIdx.x & 31;
    const int w = threadIdx.x >> 5;
    const int p = blockIdx.x * 2 + w;

    const float* q = g_Q + (size_t)p * DM;
    const float* k = g_K + (size_t)p * DM;
    const float* v = g_V + (size_t)p * DM;
    float* qs = sm[w];
    float* ks = qs + 1088;
    float* vs = ks + 1088;
    float* at = vs + 1088;

#pragma unroll
    for (int t = lane; t < 256; t += 32) {   // 256 float4 per row of 1024
        int i = t >> 4;
        int d = (t & 15) * 4;
        int off = i * 68 + d;
        *(float4*)&qs[off] = *(const float4*)(q + t * 4);
        *(float4*)&ks[off] = *(const float4*)(k + t * 4);
        *(float4*)&vs[off] = *(const float4*)(v + t * 4);
    }
    __syncwarp();

    // att: lane owns i in {2bi, 2bi+1}, j in {4bj .. 4bj+3}
    const int bi = lane >> 2;
    const int bj = lane & 3;
    float acc[2][4];
#pragma unroll
    for (int u = 0; u < 2; u++)
#pragma unroll
        for (int jv = 0; jv < 4; jv++) acc[u][jv] = 0.f;

#pragma unroll
    for (int d = 0; d < 64; d += 4) {
        float4 q0 = *(float4*)&qs[(2 * bi) * 68 + d];
        float4 q1 = *(float4*)&qs[(2 * bi + 1) * 68 + d];
#pragma unroll
        for (int jv = 0; jv < 4; jv++) {
            float4 kv = *(float4*)&ks[(4 * bj + jv) * 68 + d];
            acc[0][jv] += q0.x * kv.x + q0.y * kv.y + q0.z * kv.z + q0.w * kv.w;
            acc[1][jv] += q1.x * kv.x + q1.y * kv.y + q1.z * kv.z + q1.w * kv.w;
        }
    }
#pragma unroll
    for (int u = 0; u < 2; u++)
#pragma unroll
        for (int jv = 0; jv < 4; jv++)
            at[(2 * bi + u) * 17 + 4 * bj + jv] = acc[u][jv];
    __syncwarp();

    // softmax over j (exact fp32)
    if (lane < 16) {
        float* row = &at[lane * 17];
        float m = row[0];
#pragma unroll
        for (int j = 1; j < 16; j++) m = fmaxf(m, row[j]);
        float ssum = 0.f;
#pragma unroll
        for (int j = 0; j < 16; j++) {
            float e = __expf((row[j] - m) * 0.125f);
            row[j] = e;
            ssum += e;
        }
        float inv = 1.f / ssum;
#pragma unroll
        for (int j = 0; j < 16; j++) row[j] *= inv;
    }
    __syncwarp();

    // out: lane owns i in {2bi, 2bi+1}, d4-block bd (d = (4bd+v4)*4)
    const int bd = lane & 3;
    float4 o[2][4];
#pragma unroll
    for (int u = 0; u < 2; u++)
#pragma unroll
        for (int v4 = 0; v4 < 4; v4++) o[u][v4] = make_float4(0.f, 0.f, 0.f, 0.f);

#pragma unroll
    for (int j = 0; j < 16; j++) {
        float a0 = at[(2 * bi) * 17 + j];
        float a1 = at[(2 * bi + 1) * 17 + j];
#pragma unroll
        for (int v4 = 0; v4 < 4; v4++) {
            float4 vv = *(float4*)&vs[j * 68 + (4 * bd + v4) * 4];
            o[0][v4].x += a0 * vv.x; o[0][v4].y += a0 * vv.y;
            o[0][v4].z += a0 * vv.z; o[0][v4].w += a0 * vv.w;
            o[1][v4].x += a1 * vv.x; o[1][v4].y += a1 * vv.y;
            o[1][v4].z += a1 * vv.z; o[1][v4].w += a1 * vv.w;
        }
    }

    const int n = p >> 12;
    const int s = p & 4095;
    const size_t base = (size_t)n * SEQ * DM + (size_t)(s >> 4) * DM + (size_t)(s & 15) * 64;
#pragma unroll
    for (int u = 0; u < 2; u++) {
        int i = 2 * bi + u;
        size_t rowoff = base + (size_t)i * 256 * DM;
#pragma unroll
        for (int v4 = 0; v4 < 4; v4++)
            *(float4*)&g_MID[rowoff + (4 * bd + v4) * 4] = o[u][v4];
    }
}

extern "C" void kernel_launch(void* const* d_in, const int* in_sizes, int n_in,
                              void* d_out, int out_size) {
    (void)in_sizes; (void)n_in; (void)out_size;
    const float* x  = (const float*)d_in[0];
    const float* Wq = (const float*)d_in[1];
    const float* Wk = (const float*)d_in[2];
    const float* Wv = (const float*)d_in[3];
    const float* Wo = (const float*)d_in[4];
    const float* bo = (const float*)d_in[5];
    float* out = (float*)d_out;

    // 1) fused QKV projection: N = 3*1024 columns, M = 32768
    gemm_k<0><<<dim3(24, 256), 256>>>(x, Wq, Wk, Wv, nullptr, nullptr);
    // 2) per-token attention over heads + scrambled-reshape scatter
    attn_k<<<MTOT / 2, 64>>>();
    // 3) output projection + bias
    gemm_k<1><<<dim3(8, 256), 256>>>(nullptr, Wo, nullptr, nullptr, bo, out);
}

// round 4
// speedup vs baseline: 1.7562x; 1.7562x over previous
#include <cuda_runtime.h>
#include <cuda_fp16.h>
#include <cstdint>

#define SEQ 4096
#define DM 1024
#define MTOT 32768

// ---- scratch (device globals: sanctioned no-alloc workaround) ----
__device__ __half g_Q[(size_t)MTOT * DM];
__device__ __half g_K[(size_t)MTOT * DM];
__device__ __half g_V[(size_t)MTOT * DM];
__device__ __half g_MID[(size_t)MTOT * DM];
__device__ __half g_X[(size_t)MTOT * DM];         // fp16 x
__device__ __half g_W[(size_t)3 * DM * DM];       // fp16 [Wq;Wk;Wv]
__device__ __half g_Wo[(size_t)DM * DM];          // fp16 Wo

// ---------------------------------------------------------------------------
// helpers
// ---------------------------------------------------------------------------
__device__ __forceinline__ uint32_t smem_u32(const void* p) {
    uint32_t a;
    asm("{ .reg .u64 t; cvta.to.shared.u64 t, %1; cvt.u32.u64 %0, t; }" : "=r"(a) : "l"(p));
    return a;
}
__device__ __forceinline__ void cpasync16(uint32_t dst, const void* src) {
    asm volatile("cp.async.cg.shared.global [%0], [%1], 16;" :: "r"(dst), "l"(src) : "memory");
}
__device__ __forceinline__ void ldsm4(uint32_t* r, uint32_t addr) {
    asm volatile("ldmatrix.sync.aligned.m8n8.x4.shared.b16 {%0,%1,%2,%3}, [%4];"
                 : "=r"(r[0]), "=r"(r[1]), "=r"(r[2]), "=r"(r[3]) : "r"(addr));
}
__device__ __forceinline__ void mma_f16(float* c, const uint32_t* a, const uint32_t* b) {
    asm volatile(
        "mma.sync.aligned.m16n8k16.row.col.f32.f16.f16.f32 "
        "{%0,%1,%2,%3}, {%4,%5,%6,%7}, {%8,%9}, {%0,%1,%2,%3};\n"
        : "+f"(c[0]), "+f"(c[1]), "+f"(c[2]), "+f"(c[3])
        : "r"(a[0]), "r"(a[1]), "r"(a[2]), "r"(a[3]), "r"(b[0]), "r"(b[1]));
}

// ---------------------------------------------------------------------------
// fp32 -> fp16 convert (8 elements / thread)
// ---------------------------------------------------------------------------
__global__ void __launch_bounds__(256) cvt_h(const float4* __restrict__ src,
                                             uint4* __restrict__ dst, int n8) {
    int i = blockIdx.x * 256 + threadIdx.x;
    if (i < n8) {
        float4 a = src[2 * i], b = src[2 * i + 1];
        uint4 o;
        *(__half2*)&o.x = __floats2half2_rn(a.x, a.y);
        *(__half2*)&o.y = __floats2half2_rn(a.z, a.w);
        *(__half2*)&o.z = __floats2half2_rn(b.x, b.y);
        *(__half2*)&o.w = __floats2half2_rn(b.z, b.w);
        dst[i] = o;
    }
}

// ---------------------------------------------------------------------------
// fp16 GEMM: C[m,n] = sum_k A[m,k]*B[n,k].  Tile 128x128xK1024, BK=32 halves.
// 256 threads, warp grid 4(m) x 2(n) -> warp tile 32x64.
// 4-stage cp.async pipeline; smem rows pitched 80B -> ldmatrix conflict-free.
// MODE 0: A=g_X, B=g_W (3072 rows), C -> g_Q/g_K/g_V (half). grid (24, 256)
// MODE 1: A=g_MID, B=g_Wo, C = out fp32 + bias.              grid (8, 256)
// ---------------------------------------------------------------------------
#define PITCH 80
#define AB_BYTES (128 * PITCH)             // 10240 per operand
#define STAGE_BYTES (2 * AB_BYTES)         // 20480
#define NST 4
#define GSMEM (NST * STAGE_BYTES)          // 81920

template <int MODE>
__global__ void __launch_bounds__(256, 2) gemm_h(const float* __restrict__ bias,
                                                 float* __restrict__ Cout) {
    extern __shared__ uint8_t sm_raw[];
    const uint32_t sb = smem_u32(sm_raw);
    const int tid = threadIdx.x;
    const int lane = tid & 31;
    const int wid = tid >> 5;
    const int wm = wid & 3;          // 0..3 (m)
    const int wn = wid >> 2;         // 0..1 (n)

    const int m0 = blockIdx.y * 128;
    const int n0 = blockIdx.x * 128;
    const __half* A = (MODE == 0) ? g_X : g_MID;
    const __half* B = (MODE == 0) ? g_W : g_Wo;
    const __half* Ag = A + (size_t)m0 * DM;
    const __half* Bg = B + (size_t)n0 * DM;

    // cp.async chunk assignment: 512 A-chunks + 512 B-chunks of 16B, 4/thread
    const int r0c = tid >> 2, c0c = tid & 3;           // chunk tid
    const int r1c = r0c + 64;                          // chunk tid+256

    // ldmatrix base offsets (within a stage)
    uint32_t aBase[2];
#pragma unroll
    for (int mt = 0; mt < 2; mt++) {
        int row = wm * 32 + mt * 16 + (lane & 15);
        aBase[mt] = row * PITCH + (lane >> 4) * 16;
    }
    uint32_t bBase[4];
#pragma unroll
    for (int np = 0; np < 4; np++) {
        int row = wn * 64 + np * 16 + (lane >> 4) * 8 + (lane & 7);
        bBase[np] = AB_BYTES + row * PITCH + ((lane >> 3) & 1) * 16;
    }

    float acc[2][8][4];
#pragma unroll
    for (int mt = 0; mt < 2; mt++)
#pragma unroll
        for (int nt = 0; nt < 8; nt++)
#pragma unroll
            for (int i = 0; i < 4; i++) acc[mt][nt][i] = 0.f;

    // ---- prologue: stages 0..2 ----
#pragma unroll
    for (int s = 0; s < NST - 1; s++) {
        uint32_t st = sb + s * STAGE_BYTES;
        const __half* a = Ag + s * 32;
        const __half* b = Bg + s * 32;
        cpasync16(st + r0c * PITCH + c0c * 16, a + (size_t)r0c * DM + c0c * 8);
        cpasync16(st + r1c * PITCH + c0c * 16, a + (size_t)r1c * DM + c0c * 8);
        cpasync16(st + AB_BYTES + r0c * PITCH + c0c * 16, b + (size_t)r0c * DM + c0c * 8);
        cpasync16(st + AB_BYTES + r1c * PITCH + c0c * 16, b + (size_t)r1c * DM + c0c * 8);
        asm volatile("cp.async.commit_group;" ::: "memory");
    }

#pragma unroll 1
    for (int ks = 0; ks < 32; ks++) {
        asm volatile("cp.async.wait_group 2;" ::: "memory");
        __syncthreads();

        // issue stage ks+3 (into slot (ks-1)&3, safe after the barrier)
        if (ks + NST - 1 < 32) {
            int s = ks + NST - 1;
            uint32_t st = sb + (s & 3) * STAGE_BYTES;
            const __half* a = Ag + s * 32;
            const __half* b = Bg + s * 32;
            cpasync16(st + r0c * PITCH + c0c * 16, a + (size_t)r0c * DM + c0c * 8);
            cpasync16(st + r1c * PITCH + c0c * 16, a + (size_t)r1c * DM + c0c * 8);
            cpasync16(st + AB_BYTES + r0c * PITCH + c0c * 16, b + (size_t)r0c * DM + c0c * 8);
            cpasync16(st + AB_BYTES + r1c * PITCH + c0c * 16, b + (size_t)r1c * DM + c0c * 8);
        }
        asm volatile("cp.async.commit_group;" ::: "memory");

        const uint32_t st = sb + (ks & 3) * STAGE_BYTES;
#pragma unroll
        for (int kk = 0; kk < 2; kk++) {
            uint32_t a[2][4], b[4][4];
#pragma unroll
            for (int mt = 0; mt < 2; mt++) ldsm4(a[mt], st + aBase[mt] + kk * 32);
#pragma unroll
            for (int np = 0; np < 4; np++) ldsm4(b[np], st + bBase[np] + kk * 32);
#pragma unroll
            for (int mt = 0; mt < 2; mt++)
#pragma unroll
                for (int nt = 0; nt < 8; nt++)
                    mma_f16(acc[mt][nt], a[mt], &b[nt >> 1][(nt & 1) * 2]);
        }
    }

    // ---- epilogue ----
    if (MODE == 0) {
        __half* Cb = (n0 < 1024) ? g_Q : (n0 < 2048) ? g_K : g_V;
        const int col0 = (n0 & 1023) + wn * 64;
#pragma unroll
        for (int mt = 0; mt < 2; mt++) {
            const int r = m0 + wm * 32 + mt * 16 + (lane >> 2);
#pragma unroll
            for (int nt = 0; nt < 8; nt++) {
                const int c = col0 + nt * 8 + 2 * (lane & 3);
                *(__half2*)&Cb[(size_t)r * DM + c] =
                    __floats2half2_rn(acc[mt][nt][0], acc[mt][nt][1]);
                *(__half2*)&Cb[(size_t)(r + 8) * DM + c] =
                    __floats2half2_rn(acc[mt][nt][2], acc[mt][nt][3]);
            }
        }
    } else {
        const int col0 = n0 + wn * 64;
#pragma unroll
        for (int mt = 0; mt < 2; mt++) {
            const int r = m0 + wm * 32 + mt * 16 + (lane >> 2);
#pragma unroll
            for (int nt = 0; nt < 8; nt++) {
                const int c = col0 + nt * 8 + 2 * (lane & 3);
                const float b0 = bias[c], b1 = bias[c + 1];
                *(float2*)&Cout[(size_t)r * DM + c] =
                    make_float2(acc[mt][nt][0] + b0, acc[mt][nt][1] + b1);
                *(float2*)&Cout[(size_t)(r + 8) * DM + c] =
                    make_float2(acc[mt][nt][2] + b0, acc[mt][nt][3] + b1);
            }
        }
    }
}

// ---------------------------------------------------------------------------
// Attention-over-heads, fp16 in / fp16 out, fp32 math.
// One warp per token p. att over H=16 heads, softmax, weighted V.
// Scatter: MID[n, i*256 + (s>>4), (s&15)*64 + d] = o[i,d]
// ---------------------------------------------------------------------------
__global__ void __launch_bounds__(64) attn_k() {
    __shared__ float sm[2][3536];   // q[16*68] k[16*68] v[16*68] att[16*17]
    const int lane = threadIdx.x & 31;
    const int w = threadIdx.x >> 5;
    const int p = blockIdx.x * 2 + w;

    const __half* q = g_Q + (size_t)p * DM;
    const __half* k = g_K + (size_t)p * DM;
    const __half* v = g_V + (size_t)p * DM;
    float* qs = sm[w];
    float* ks = qs + 1088;
    float* vs = ks + 1088;
    float* at = vs + 1088;

#pragma unroll
    for (int t = lane; t < 128; t += 32) {   // 128 chunks of 8 halves
        const int i = t >> 3;
        const int d = (t & 7) * 8;
        const int off = i * 68 + d;
        uint4 uq = *(const uint4*)(q + t * 8);
        uint4 uk = *(const uint4*)(k + t * 8);
        uint4 uv = *(const uint4*)(v + t * 8);
        const __half2* hq = (const __half2*)&uq;
        const __half2* hk = (const __half2*)&uk;
        const __half2* hv = (const __half2*)&uv;
        float2 f0, f1;
        f0 = __half22float2(hq[0]); f1 = __half22float2(hq[1]);
        *(float4*)&qs[off] = make_float4(f0.x, f0.y, f1.x, f1.y);
        f0 = __half22float2(hq[2]); f1 = __half22float2(hq[3]);
        *(float4*)&qs[off + 4] = make_float4(f0.x, f0.y, f1.x, f1.y);
        f0 = __half22float2(hk[0]); f1 = __half22float2(hk[1]);
        *(float4*)&ks[off] = make_float4(f0.x, f0.y, f1.x, f1.y);
        f0 = __half22float2(hk[2]); f1 = __half22float2(hk[3]);
        *(float4*)&ks[off + 4] = make_float4(f0.x, f0.y, f1.x, f1.y);
        f0 = __half22float2(hv[0]); f1 = __half22float2(hv[1]);
        *(float4*)&vs[off] = make_float4(f0.x, f0.y, f1.x, f1.y);
        f0 = __half22float2(hv[2]); f1 = __half22float2(hv[3]);
        *(float4*)&vs[off + 4] = make_float4(f0.x, f0.y, f1.x, f1.y);
    }
    __syncwarp();

    const int bi = lane >> 2;
    const int bj = lane & 3;
    float acc[2][4];
#pragma unroll
    for (int u = 0; u < 2; u++)
#pragma unroll
        for (int jv = 0; jv < 4; jv++) acc[u][jv] = 0.f;

#pragma unroll
    for (int d = 0; d < 64; d += 4) {
        float4 q0 = *(float4*)&qs[(2 * bi) * 68 + d];
        float4 q1 = *(float4*)&qs[(2 * bi + 1) * 68 + d];
#pragma unroll
        for (int jv = 0; jv < 4; jv++) {
            float4 kv = *(float4*)&ks[(4 * bj + jv) * 68 + d];
            acc[0][jv] += q0.x * kv.x + q0.y * kv.y + q0.z * kv.z + q0.w * kv.w;
            acc[1][jv] += q1.x * kv.x + q1.y * kv.y + q1.z * kv.z + q1.w * kv.w;
        }
    }
#pragma unroll
    for (int u = 0; u < 2; u++)
#pragma unroll
        for (int jv = 0; jv < 4; jv++)
            at[(2 * bi + u) * 17 + 4 * bj + jv] = acc[u][jv];
    __syncwarp();

    if (lane < 16) {
        float* row = &at[lane * 17];
        float m = row[0];
#pragma unroll
        for (int j = 1; j < 16; j++) m = fmaxf(m, row[j]);
        float ssum = 0.f;
#pragma unroll
        for (int j = 0; j < 16; j++) {
            float e = __expf((row[j] - m) * 0.125f);
            row[j] = e;
            ssum += e;
        }
        float inv = 1.f / ssum;
#pragma unroll
        for (int j = 0; j < 16; j++) row[j] *= inv;
    }
    __syncwarp();

    const int bd = lane & 3;
    float4 o[2][4];
#pragma unroll
    for (int u = 0; u < 2; u++)
#pragma unroll
        for (int v4 = 0; v4 < 4; v4++) o[u][v4] = make_float4(0.f, 0.f, 0.f, 0.f);

#pragma unroll
    for (int j = 0; j < 16; j++) {
        float a0 = at[(2 * bi) * 17 + j];
        float a1 = at[(2 * bi + 1) * 17 + j];
#pragma unroll
        for (int v4 = 0; v4 < 4; v4++) {
            float4 vv = *(float4*)&vs[j * 68 + (4 * bd + v4) * 4];
            o[0][v4].x += a0 * vv.x; o[0][v4].y += a0 * vv.y;
            o[0][v4].z += a0 * vv.z; o[0][v4].w += a0 * vv.w;
            o[1][v4].x += a1 * vv.x; o[1][v4].y += a1 * vv.y;
            o[1][v4].z += a1 * vv.z; o[1][v4].w += a1 * vv.w;
        }
    }

    const int n = p >> 12;
    const int s = p & 4095;
    const size_t base = (size_t)n * SEQ * DM + (size_t)(s >> 4) * DM + (size_t)(s & 15) * 64;
#pragma unroll
    for (int u = 0; u < 2; u++) {
        const int i = 2 * bi + u;
        const size_t rowoff = base + (size_t)i * 256 * DM;
#pragma unroll
        for (int v4 = 0; v4 < 4; v4++) {
            float4 ov = o[u][v4];
            uint2 wv;
            *(__half2*)&wv.x = __floats2half2_rn(ov.x, ov.y);
            *(__half2*)&wv.y = __floats2half2_rn(ov.z, ov.w);
            *(uint2*)&g_MID[rowoff + (4 * bd + v4) * 4] = wv;
        }
    }
}

extern "C" void kernel_launch(void* const* d_in, const int* in_sizes, int n_in,
                              void* d_out, int out_size) {
    (void)in_sizes; (void)n_in; (void)out_size;
    const float* x  = (const float*)d_in[0];
    const float* Wq = (const float*)d_in[1];
    const float* Wk = (const float*)d_in[2];
    const float* Wv = (const float*)d_in[3];
    const float* Wo = (const float*)d_in[4];
    const float* bo = (const float*)d_in[5];
    float* out = (float*)d_out;

    cudaFuncSetAttribute(gemm_h<0>, cudaFuncAttributeMaxDynamicSharedMemorySize, GSMEM);
    cudaFuncSetAttribute(gemm_h<1>, cudaFuncAttributeMaxDynamicSharedMemorySize, GSMEM);

    __half* gX; __half* gW; __half* gWo;
    cudaGetSymbolAddress((void**)&gX, g_X);
    cudaGetSymbolAddress((void**)&gW, g_W);
    cudaGetSymbolAddress((void**)&gWo, g_Wo);

    // fp32 -> fp16 converts
    cvt_h<<<MTOT * DM / 8 / 256, 256>>>((const float4*)x, (uint4*)gX, MTOT * DM / 8);
    cvt_h<<<512, 256>>>((const float4*)Wq, (uint4*)gW, DM * DM / 8);
    cvt_h<<<512, 256>>>((const float4*)Wk, (uint4*)(gW + (size_t)DM * DM), DM * DM / 8);
    cvt_h<<<512, 256>>>((const float4*)Wv, (uint4*)(gW + (size_t)2 * DM * DM), DM * DM / 8);
    cvt_h<<<512, 256>>>((const float4*)Wo, (uint4*)gWo, DM * DM / 8);

    // 1) fused QKV projection (N = 3072)
    gemm_h<0><<<dim3(24, 256), 256, GSMEM>>>(nullptr, nullptr);
    // 2) attention-over-heads + scrambled reshape (fp16 out)
    attn_k<<<MTOT / 2, 64>>>();
    // 3) output projection + bias (fp32 out)
    gemm_h<1><<<dim3(8, 256), 256, GSMEM>>>(bo, out);
}

// round 5
// speedup vs baseline: 2.2644x; 1.2894x over previous
#include <cuda_runtime.h>
#include <cuda_fp16.h>
#include <cstdint>

#define SEQ 4096
#define DM 1024
#define MTOT 32768

// ---- scratch (device globals: sanctioned no-alloc workaround) ----
__device__ __half g_Q[(size_t)MTOT * DM];
__device__ __half g_K[(size_t)MTOT * DM];
__device__ __half g_V[(size_t)MTOT * DM];
__device__ __half g_MID[(size_t)MTOT * DM];
__device__ __half g_X[(size_t)MTOT * DM];         // fp16 x
__device__ __half g_W[(size_t)3 * DM * DM];       // fp16 [Wq;Wk;Wv]
__device__ __half g_Wo[(size_t)DM * DM];          // fp16 Wo

// ---------------------------------------------------------------------------
// helpers
// ---------------------------------------------------------------------------
__device__ __forceinline__ uint32_t smem_u32(const void* p) {
    uint32_t a;
    asm("{ .reg .u64 t; cvta.to.shared.u64 t, %1; cvt.u32.u64 %0, t; }" : "=r"(a) : "l"(p));
    return a;
}
__device__ __forceinline__ void cpasync16(uint32_t dst, const void* src) {
    asm volatile("cp.async.cg.shared.global [%0], [%1], 16;" :: "r"(dst), "l"(src) : "memory");
}
__device__ __forceinline__ void ldsm4(uint32_t* r, uint32_t addr) {
    asm volatile("ldmatrix.sync.aligned.m8n8.x4.shared.b16 {%0,%1,%2,%3}, [%4];"
                 : "=r"(r[0]), "=r"(r[1]), "=r"(r[2]), "=r"(r[3]) : "r"(addr));
}
__device__ __forceinline__ void mma_f16(float* c, const uint32_t* a, const uint32_t* b) {
    asm volatile(
        "mma.sync.aligned.m16n8k16.row.col.f32.f16.f16.f32 "
        "{%0,%1,%2,%3}, {%4,%5,%6,%7}, {%8,%9}, {%0,%1,%2,%3};\n"
        : "+f"(c[0]), "+f"(c[1]), "+f"(c[2]), "+f"(c[3])
        : "r"(a[0]), "r"(a[1]), "r"(a[2]), "r"(a[3]), "r"(b[0]), "r"(b[1]));
}

// ---------------------------------------------------------------------------
// fp32 -> fp16 convert (8 elements / thread)
// ---------------------------------------------------------------------------
__global__ void __launch_bounds__(256) cvt_h(const float4* __restrict__ src,
                                             uint4* __restrict__ dst, int n8) {
    int i = blockIdx.x * 256 + threadIdx.x;
    if (i < n8) {
        float4 a = src[2 * i], b = src[2 * i + 1];
        uint4 o;
        *(__half2*)&o.x = __floats2half2_rn(a.x, a.y);
        *(__half2*)&o.y = __floats2half2_rn(a.z, a.w);
        *(__half2*)&o.z = __floats2half2_rn(b.x, b.y);
        *(__half2*)&o.w = __floats2half2_rn(b.z, b.w);
        dst[i] = o;
    }
}

// ---------------------------------------------------------------------------
// fp16 GEMM: C[m,n] = sum_k A[m,k]*B[n,k]. Tile 128x128, BK=64 halves (128B
// rows, XOR-16B swizzle -> conflict-free cp.async stores AND ldmatrix loads).
// 256 threads, warp grid 2(m) x 4(n), warp tile 64x32, accum 64 regs.
// 3-stage cp.async pipeline, 96KB smem -> 2 CTAs/SM (16 warps).
// MODE 0: A=g_X, B=g_W (3072 rows), C -> g_Q/g_K/g_V (half). grid (24, 256)
// MODE 1: A=g_MID, B=g_Wo, C = out fp32 + bias.              grid (8, 256)
// ---------------------------------------------------------------------------
#define AB_BYTES 16384                     // 128 rows * 128B
#define STAGE_BYTES (2 * AB_BYTES)         // 32768
#define NST 3
#define GSMEM (NST * STAGE_BYTES)          // 98304

template <int MODE>
__global__ void __launch_bounds__(256, 2) gemm_h(const float* __restrict__ bias,
                                                 float* __restrict__ Cout) {
    extern __shared__ uint8_t sm_raw[];
    const uint32_t sb = smem_u32(sm_raw);
    const int tid = threadIdx.x;
    const int lane = tid & 31;
    const int wid = tid >> 5;
    const int wm = wid >> 2;         // 0..1 (m, 64 rows each)
    const int wn = wid & 3;          // 0..3 (n, 32 cols each)

    const int m0 = blockIdx.y * 128;
    const int n0 = blockIdx.x * 128;
    const __half* A = (MODE == 0) ? g_X : g_MID;
    const __half* B = (MODE == 0) ? g_W : g_Wo;
    const __half* Ag = A + (size_t)m0 * DM;
    const __half* Bg = B + (size_t)n0 * DM;

    // cp.async: 1024 A-chunks + 1024 B-chunks of 16B per stage, 4+4 per thread
    // chunk id = tid + i*256 -> row = id>>3 (0..127), c = id&7; swizzle c^(r&7)
    int srow[4], ssw[4];
#pragma unroll
    for (int i = 0; i < 4; i++) {
        int id = tid + i * 256;
        int r = id >> 3, c = id & 7;
        srow[i] = r;
        ssw[i] = r * 128 + ((c ^ (r & 7)) << 4);
    }
    const int scol8 = (tid & 7) * 8;   // gmem half-offset of this thread's chunk

    // ldmatrix bases: A frag mt rows wm*64+mt*16+(lane&15); hi chunk = lane>>4
    uint32_t aOff[4]; int aSw[4];
    const int aHi = lane >> 4;
#pragma unroll
    for (int mt = 0; mt < 4; mt++) {
        int r = wm * 64 + mt * 16 + (lane & 15);
        aOff[mt] = r * 128;
        aSw[mt] = r & 7;
    }
    // B frag np rows wn*32+np*16+((lane>>4)<<3)+(lane&7); hi = (lane>>3)&1
    uint32_t bOff[2]; int bSw[2];
    const int bHi = (lane >> 3) & 1;
#pragma unroll
    for (int np = 0; np < 2; np++) {
        int r = wn * 32 + np * 16 + ((lane >> 4) << 3) + (lane & 7);
        bOff[np] = AB_BYTES + r * 128;
        bSw[np] = r & 7;
    }

    float acc[4][4][4];
#pragma unroll
    for (int mt = 0; mt < 4; mt++)
#pragma unroll
        for (int nt = 0; nt < 4; nt++)
#pragma unroll
            for (int i = 0; i < 4; i++) acc[mt][nt][i] = 0.f;

    // ---- prologue: stages 0,1 ----
#pragma unroll
    for (int s = 0; s < NST - 1; s++) {
        const uint32_t st = sb + s * STAGE_BYTES;
        const __half* a = Ag + s * 64;
        const __half* b = Bg + s * 64;
#pragma unroll
        for (int i = 0; i < 4; i++) {
            cpasync16(st + ssw[i], a + (size_t)srow[i] * DM + scol8);
            cpasync16(st + AB_BYTES + ssw[i], b + (size_t)srow[i] * DM + scol8);
        }
        asm volatile("cp.async.commit_group;" ::: "memory");
    }

#pragma unroll 1
    for (int ks = 0; ks < 16; ks++) {
        asm volatile("cp.async.wait_group 1;" ::: "memory");
        __syncthreads();

        if (ks + NST - 1 < 16) {
            const int s = ks + NST - 1;
            const uint32_t st = sb + (s % NST) * STAGE_BYTES;
            const __half* a = Ag + s * 64;
            const __half* b = Bg + s * 64;
#pragma unroll
            for (int i = 0; i < 4; i++) {
                cpasync16(st + ssw[i], a + (size_t)srow[i] * DM + scol8);
                cpasync16(st + AB_BYTES + ssw[i], b + (size_t)srow[i] * DM + scol8);
            }
        }
        asm volatile("cp.async.commit_group;" ::: "memory");

        const uint32_t st = sb + (ks % NST) * STAGE_BYTES;
#pragma unroll
        for (int kk = 0; kk < 4; kk++) {
            uint32_t a[4][4], b[2][4];
#pragma unroll
            for (int mt = 0; mt < 4; mt++)
                ldsm4(a[mt], st + aOff[mt] + (((kk * 2 + aHi) ^ aSw[mt]) << 4));
#pragma unroll
            for (int np = 0; np < 2; np++)
                ldsm4(b[np], st + bOff[np] + (((kk * 2 + bHi) ^ bSw[np]) << 4));
#pragma unroll
            for (int mt = 0; mt < 4; mt++)
#pragma unroll
                for (int nt = 0; nt < 4; nt++)
                    mma_f16(acc[mt][nt], a[mt], &b[nt >> 1][(nt & 1) * 2]);
        }
    }

    // ---- epilogue ----
    if (MODE == 0) {
        __half* Cb = (n0 < 1024) ? g_Q : (n0 < 2048) ? g_K : g_V;
        const int col0 = (n0 & 1023) + wn * 32;
#pragma unroll
        for (int mt = 0; mt < 4; mt++) {
            const int r = m0 + wm * 64 + mt * 16 + (lane >> 2);
#pragma unroll
            for (int nt = 0; nt < 4; nt++) {
                const int c = col0 + nt * 8 + 2 * (lane & 3);
                *(__half2*)&Cb[(size_t)r * DM + c] =
                    __floats2half2_rn(acc[mt][nt][0], acc[mt][nt][1]);
                *(__half2*)&Cb[(size_t)(r + 8) * DM + c] =
                    __floats2half2_rn(acc[mt][nt][2], acc[mt][nt][3]);
            }
        }
    } else {
        const int col0 = n0 + wn * 32;
#pragma unroll
        for (int mt = 0; mt < 4; mt++) {
            const int r = m0 + wm * 64 + mt * 16 + (lane >> 2);
#pragma unroll
            for (int nt = 0; nt < 4; nt++) {
                const int c = col0 + nt * 8 + 2 * (lane & 3);
                const float b0 = bias[c], b1 = bias[c + 1];
                *(float2*)&Cout[(size_t)r * DM + c] =
                    make_float2(acc[mt][nt][0] + b0, acc[mt][nt][1] + b1);
                *(float2*)&Cout[(size_t)(r + 8) * DM + c] =
                    make_float2(acc[mt][nt][2] + b0, acc[mt][nt][3] + b1);
            }
        }
    }
}

// ---------------------------------------------------------------------------
// Attention-over-heads, fp16 in / fp16 out, fp32 math.
// One warp per token p. Scatter: MID[n, i*256 + (s>>4), (s&15)*64 + d]
// ---------------------------------------------------------------------------
__global__ void __launch_bounds__(64) attn_k() {
    __shared__ float sm[2][3536];
    const int lane = threadIdx.x & 31;
    const int w = threadIdx.x >> 5;
    const int p = blockIdx.x * 2 + w;

    const __half* q = g_Q + (size_t)p * DM;
    const __half* k = g_K + (size_t)p * DM;
    const __half* v = g_V + (size_t)p * DM;
    float* qs = sm[w];
    float* ks = qs + 1088;
    float* vs = ks + 1088;
    float* at = vs + 1088;

#pragma unroll
    for (int t = lane; t < 128; t += 32) {
        const int i = t >> 3;
        const int d = (t & 7) * 8;
        const int off = i * 68 + d;
        uint4 uq = *(const uint4*)(q + t * 8);
        uint4 uk = *(const uint4*)(k + t * 8);
        uint4 uv = *(const uint4*)(v + t * 8);
        const __half2* hq = (const __half2*)&uq;
        const __half2* hk = (const __half2*)&uk;
        const __half2* hv = (const __half2*)&uv;
        float2 f0, f1;
        f0 = __half22float2(hq[0]); f1 = __half22float2(hq[1]);
        *(float4*)&qs[off] = make_float4(f0.x, f0.y, f1.x, f1.y);
        f0 = __half22float2(hq[2]); f1 = __half22float2(hq[3]);
        *(float4*)&qs[off + 4] = make_float4(f0.x, f0.y, f1.x, f1.y);
        f0 = __half22float2(hk[0]); f1 = __half22float2(hk[1]);
        *(float4*)&ks[off] = make_float4(f0.x, f0.y, f1.x, f1.y);
        f0 = __half22float2(hk[2]); f1 = __half22float2(hk[3]);
        *(float4*)&ks[off + 4] = make_float4(f0.x, f0.y, f1.x, f1.y);
        f0 = __half22float2(hv[0]); f1 = __half22float2(hv[1]);
        *(float4*)&vs[off] = make_float4(f0.x, f0.y, f1.x, f1.y);
        f0 = __half22float2(hv[2]); f1 = __half22float2(hv[3]);
        *(float4*)&vs[off + 4] = make_float4(f0.x, f0.y, f1.x, f1.y);
    }
    __syncwarp();

    const int bi = lane >> 2;
    const int bj = lane & 3;
    float acc[2][4];
#pragma unroll
    for (int u = 0; u < 2; u++)
#pragma unroll
        for (int jv = 0; jv < 4; jv++) acc[u][jv] = 0.f;

#pragma unroll
    for (int d = 0; d < 64; d += 4) {
        float4 q0 = *(float4*)&qs[(2 * bi) * 68 + d];
        float4 q1 = *(float4*)&qs[(2 * bi + 1) * 68 + d];
#pragma unroll
        for (int jv = 0; jv < 4; jv++) {
            float4 kv = *(float4*)&ks[(4 * bj + jv) * 68 + d];
            acc[0][jv] += q0.x * kv.x + q0.y * kv.y + q0.z * kv.z + q0.w * kv.w;
            acc[1][jv] += q1.x * kv.x + q1.y * kv.y + q1.z * kv.z + q1.w * kv.w;
        }
    }
#pragma unroll
    for (int u = 0; u < 2; u++)
#pragma unroll
        for (int jv = 0; jv < 4; jv++)
            at[(2 * bi + u) * 17 + 4 * bj + jv] = acc[u][jv];
    __syncwarp();

    if (lane < 16) {
        float* row = &at[lane * 17];
        float m = row[0];
#pragma unroll
        for (int j = 1; j < 16; j++) m = fmaxf(m, row[j]);
        float ssum = 0.f;
#pragma unroll
        for (int j = 0; j < 16; j++) {
            float e = __expf((row[j] - m) * 0.125f);
            row[j] = e;
            ssum += e;
        }
        float inv = 1.f / ssum;
#pragma unroll
        for (int j = 0; j < 16; j++) row[j] *= inv;
    }
    __syncwarp();

    const int bd = lane & 3;
    float4 o[2][4];
#pragma unroll
    for (int u = 0; u < 2; u++)
#pragma unroll
        for (int v4 = 0; v4 < 4; v4++) o[u][v4] = make_float4(0.f, 0.f, 0.f, 0.f);

#pragma unroll
    for (int j = 0; j < 16; j++) {
        float a0 = at[(2 * bi) * 17 + j];
        float a1 = at[(2 * bi + 1) * 17 + j];
#pragma unroll
        for (int v4 = 0; v4 < 4; v4++) {
            float4 vv = *(float4*)&vs[j * 68 + (4 * bd + v4) * 4];
            o[0][v4].x += a0 * vv.x; o[0][v4].y += a0 * vv.y;
            o[0][v4].z += a0 * vv.z; o[0][v4].w += a0 * vv.w;
            o[1][v4].x += a1 * vv.x; o[1][v4].y += a1 * vv.y;
            o[1][v4].z += a1 * vv.z; o[1][v4].w += a1 * vv.w;
        }
    }

    const int n = p >> 12;
    const int s = p & 4095;
    const size_t base = (size_t)n * SEQ * DM + (size_t)(s >> 4) * DM + (size_t)(s & 15) * 64;
#pragma unroll
    for (int u = 0; u < 2; u++) {
        const int i = 2 * bi + u;
        const size_t rowoff = base + (size_t)i * 256 * DM;
#pragma unroll
        for (int v4 = 0; v4 < 4; v4++) {
            float4 ov = o[u][v4];
            uint2 wv;
            *(__half2*)&wv.x = __floats2half2_rn(ov.x, ov.y);
            *(__half2*)&wv.y = __floats2half2_rn(ov.z, ov.w);
            *(uint2*)&g_MID[rowoff + (4 * bd + v4) * 4] = wv;
        }
    }
}

extern "C" void kernel_launch(void* const* d_in, const int* in_sizes, int n_in,
                              void* d_out, int out_size) {
    (void)in_sizes; (void)n_in; (void)out_size;
    const float* x  = (const float*)d_in[0];
    const float* Wq = (const float*)d_in[1];
    const float* Wk = (const float*)d_in[2];
    const float* Wv = (const float*)d_in[3];
    const float* Wo = (const float*)d_in[4];
    const float* bo = (const float*)d_in[5];
    float* out = (float*)d_out;

    cudaFuncSetAttribute(gemm_h<0>, cudaFuncAttributeMaxDynamicSharedMemorySize, GSMEM);
    cudaFuncSetAttribute(gemm_h<1>, cudaFuncAttributeMaxDynamicSharedMemorySize, GSMEM);

    __half* gX; __half* gW; __half* gWo;
    cudaGetSymbolAddress((void**)&gX, g_X);
    cudaGetSymbolAddress((void**)&gW, g_W);
    cudaGetSymbolAddress((void**)&gWo, g_Wo);

    // fp32 -> fp16 converts
    cvt_h<<<MTOT * DM / 8 / 256, 256>>>((const float4*)x, (uint4*)gX, MTOT * DM / 8);
    cvt_h<<<512, 256>>>((const float4*)Wq, (uint4*)gW, DM * DM / 8);
    cvt_h<<<512, 256>>>((const float4*)Wk, (uint4*)(gW + (size_t)DM * DM), DM * DM / 8);
    cvt_h<<<512, 256>>>((const float4*)Wv, (uint4*)(gW + (size_t)2 * DM * DM), DM * DM / 8);
    cvt_h<<<512, 256>>>((const float4*)Wo, (uint4*)gWo, DM * DM / 8);

    // 1) fused QKV projection (N = 3072)
    gemm_h<0><<<dim3(24, 256), 256, GSMEM>>>(nullptr, nullptr);
    // 2) attention-over-heads + scrambled reshape (fp16 out)
    attn_k<<<MTOT / 2, 64>>>();
    // 3) output projection + bias (fp32 out)
    gemm_h<1><<<dim3(8, 256), 256, GSMEM>>>(bo, out);
}